// round 6
// baseline (speedup 1.0000x reference)
#include <cuda_runtime.h>

// Problem constants
#define BB 16
#define CC 64
#define HH 256
#define WW 256
#define HW (HH*WW)
#define KPOS 9          // 3x3
#define JDIM (CC*KPOS)  // 576

// Scratch (no allocation allowed in kernel_launch)
__device__ float g_avg[BB*CC];          // 1024 channel means
__device__ float g_wk[BB*JDIM];         // 9216 sigmoid'd dynamic weights
__device__ int   g_cnt[BB];             // per-batch completion counters (zero-init)

// ---------------------------------------------------------------------------
// Kernel 1 (fused): per-(b,c) spatial mean; the LAST CTA of each batch also
// computes that batch's dynamic weights: wk = sigmoid(avg @ w1^T + b1).
// Saves a separate launch (~2.5us of latency).
// ---------------------------------------------------------------------------
__global__ void avg_weight_kernel(const float* __restrict__ x,
                                  const float* __restrict__ w1,
                                  const float* __restrict__ b1) {
    const int bc = blockIdx.x;
    const int b  = bc >> 6;
    const float4* p = reinterpret_cast<const float4*>(x + (size_t)bc * HW);
    const int t = threadIdx.x;     // 0..255
    float s = 0.f;
    #pragma unroll 8
    for (int i = 0; i < 64; ++i) {
        float4 v = p[i * 256 + t];
        s += (v.x + v.y) + (v.z + v.w);
    }
    __shared__ float red[256];
    red[t] = s;
    __syncthreads();
    #pragma unroll
    for (int off = 128; off > 0; off >>= 1) {
        if (t < off) red[t] += red[t + off];
        __syncthreads();
    }

    __shared__ int is_last;
    if (t == 0) {
        g_avg[bc] = red[0] * (1.0f / (float)HW);
        __threadfence();                               // publish mean
        int old = atomicAdd(&g_cnt[b], 1);
        is_last = (old == CC - 1);
        if (is_last) atomicExch(&g_cnt[b], 0);         // reset for graph replay
    }
    __syncthreads();
    if (!is_last) return;

    // Last CTA of this batch: compute 576 weights with 256 threads.
    __shared__ float av[CC];
    if (t < CC) {
        __threadfence();                               // acquire
        av[t] = g_avg[b * CC + t];
    }
    __syncthreads();
    for (int j = t; j < JDIM; j += 256) {
        float acc = b1[j];
        const float* wr = w1 + (size_t)j * CC;
        #pragma unroll 16
        for (int c = 0; c < CC; ++c) acc += av[c] * wr[c];
        g_wk[b * JDIM + j] = 1.0f / (1.0f + expf(-acc));
    }
}

// ---------------------------------------------------------------------------
// Kernel 2: depthwise 3x3 conv + conv_bias, fused with (x-y)*fs*x + y.
// Hybrid register stencil: 4 cols/thread so all wide loads/stores are fully
// coalesced (lanes contiguous); NO shuffles; horizontal halo = 2 scalar LDGs
// that hit L1 (lines owned by adjacent lanes). Rolling 3-row x 6-col window.
// 256 threads = 4 row-slices x 64 col-groups over a 32-row x 256-col tile.
// ---------------------------------------------------------------------------
#define TR 32

__device__ __forceinline__ void load_row6(const float* __restrict__ xp,
                                          int g, int col0,
                                          float& l, float4& v, float& r) {
    v = make_float4(0.f, 0.f, 0.f, 0.f);
    l = 0.f; r = 0.f;
    if ((unsigned)g < HH) {
        const float* rowp = xp + (size_t)g * WW;
        v = *reinterpret_cast<const float4*>(rowp + col0);
        if (col0 > 0)         l = __ldg(rowp + col0 - 1);
        if (col0 < WW - 4)    r = __ldg(rowp + col0 + 4);
    }
}

__global__ void __launch_bounds__(256) conv_kernel(
        const float* __restrict__ x,
        const float* __restrict__ fscale,
        const float* __restrict__ conv_bias,
        float* __restrict__ out) {
    const int bc   = blockIdx.y;          // 0..1023
    const int c    = bc & (CC - 1);
    const int row0 = blockIdx.x * TR;
    const int t    = threadIdx.x;         // 0..255
    const int cg   = t & 63;              // cols [4cg, 4cg+3]
    const int rs   = t >> 6;              // row slice 0..3 (8 rows each)
    const int g0   = row0 + rs * 8;
    const int col0 = cg * 4;

    const float* wp = g_wk + bc * KPOS;
    const float w0 = __ldg(wp + 0), w1v = __ldg(wp + 1), w2 = __ldg(wp + 2);
    const float w3 = __ldg(wp + 3), w4  = __ldg(wp + 4), w5 = __ldg(wp + 5);
    const float w6 = __ldg(wp + 6), w7  = __ldg(wp + 7), w8 = __ldg(wp + 8);
    const float cb = __ldg(conv_bias + c);
    const float fs = __ldg(fscale + c);

    const float* xp = x + (size_t)bc * HW;

    float  al, ar, bl, br;
    float4 av, bv;
    load_row6(xp, g0 - 1, col0, al, av, ar);
    load_row6(xp, g0,     col0, bl, bv, br);

    float* op = out + (size_t)bc * HW + (size_t)g0 * WW + col0;

    #pragma unroll
    for (int r = 0; r < 8; ++r) {
        float  cl, cr;
        float4 cv;
        load_row6(xp, g0 + r + 1, col0, cl, cv, cr);

        float4 o;
        {   // col0
            float y = cb + w0*al   + w1v*av.x + w2*av.y
                         + w3*bl   + w4 *bv.x + w5*bv.y
                         + w6*cl   + w7 *cv.x + w8*cv.y;
            const float xv = bv.x;
            o.x = (xv - y) * fs * xv + y;
        }
        {   // col0+1
            float y = cb + w0*av.x + w1v*av.y + w2*av.z
                         + w3*bv.x + w4 *bv.y + w5*bv.z
                         + w6*cv.x + w7 *cv.y + w8*cv.z;
            const float xv = bv.y;
            o.y = (xv - y) * fs * xv + y;
        }
        {   // col0+2
            float y = cb + w0*av.y + w1v*av.z + w2*av.w
                         + w3*bv.y + w4 *bv.z + w5*bv.w
                         + w6*cv.y + w7 *cv.z + w8*cv.w;
            const float xv = bv.z;
            o.z = (xv - y) * fs * xv + y;
        }
        {   // col0+3
            float y = cb + w0*av.z + w1v*av.w + w2*ar
                         + w3*bv.z + w4 *bv.w + w5*br
                         + w6*cv.z + w7 *cv.w + w8*cr;
            const float xv = bv.w;
            o.w = (xv - y) * fs * xv + y;
        }
        __stcs(reinterpret_cast<float4*>(op + (size_t)r * WW), o);

        al = bl; av = bv; ar = br;
        bl = cl; bv = cv; br = cr;
    }
}

// ---------------------------------------------------------------------------
// Launch: x, w1, b1, fscale, conv_bias (metadata order); out fp32.
// ---------------------------------------------------------------------------
extern "C" void kernel_launch(void* const* d_in, const int* in_sizes, int n_in,
                              void* d_out, int out_size) {
    const float* x         = (const float*)d_in[0];
    const float* w1        = (const float*)d_in[1];
    const float* b1        = (const float*)d_in[2];
    const float* fscale    = (const float*)d_in[3];
    const float* conv_bias = (const float*)d_in[4];
    float* out = (float*)d_out;

    avg_weight_kernel<<<BB * CC, 256>>>(x, w1, b1);
    conv_kernel<<<dim3(HH / TR, BB * CC), 256>>>(x, fscale, conv_bias, out);
}

// round 7
// speedup vs baseline: 1.1145x; 1.1145x over previous
#include <cuda_runtime.h>

// Problem constants
#define BB 16
#define CC 64
#define HH 256
#define WW 256
#define HW (HH*WW)
#define KPOS 9          // 3x3
#define JDIM (CC*KPOS)  // 576

// Scratch (no allocation allowed in kernel_launch)
__device__ float g_avg[BB*CC];          // 1024 channel means
__device__ float g_wk[BB*JDIM];         // 9216 sigmoid'd dynamic weights

// ---------------------------------------------------------------------------
// Kernel 1: per-(b,c) spatial mean. At DRAM roofline (81% / 6.45 TB/s).
// (R6's fused version regressed ~42us from per-CTA gpu-scope fences; split
// launches are cheaper. Keep split.)
// ---------------------------------------------------------------------------
__global__ void avg_kernel(const float* __restrict__ x) {
    const int bc = blockIdx.x;
    const float4* p = reinterpret_cast<const float4*>(x + (size_t)bc * HW);
    const int t = threadIdx.x;     // 0..255
    float s = 0.f;
    #pragma unroll 8
    for (int i = 0; i < 64; ++i) {
        float4 v = p[i * 256 + t];
        s += (v.x + v.y) + (v.z + v.w);
    }
    __shared__ float red[256];
    red[t] = s;
    __syncthreads();
    #pragma unroll
    for (int off = 128; off > 0; off >>= 1) {
        if (t < off) red[t] += red[t + off];
        __syncthreads();
    }
    if (t == 0) g_avg[bc] = red[0] * (1.0f / (float)HW);
}

// ---------------------------------------------------------------------------
// Kernel 2: dyn = avg @ w1^T + b1 ; wk = sigmoid(dyn).
// ---------------------------------------------------------------------------
__global__ void weight_kernel(const float* __restrict__ w1,
                              const float* __restrict__ b1) {
    const int b = blockIdx.x;
    const int j = threadIdx.x;   // 0..575
    __shared__ float av[CC];
    if (j < CC) av[j] = g_avg[b * CC + j];
    __syncthreads();
    float s = b1[j];
    const float* wr = w1 + (size_t)j * CC;
    #pragma unroll 16
    for (int c = 0; c < CC; ++c) s += av[c] * wr[c];
    g_wk[b * JDIM + j] = 1.0f / (1.0f + expf(-s));
}

// ---------------------------------------------------------------------------
// Kernel 3: depthwise 3x3 conv + conv_bias, fused with (x-y)*fs*x + y.
// PROVEN 79.8us @ 6084 GB/s (R6). Hybrid register stencil: 4 cols/thread,
// fully coalesced LDG.128/STG.128, NO shuffles; horizontal halo = 2 scalar
// LDGs (L1 hits on neighbor lanes' lines). Rolling 3-row x 6-col window.
// 256 threads = 4 row-slices x 64 col-groups over a 32-row x 256-col tile.
// Streaming stores (__stcs) keep dead output lines from evicting x.
// ---------------------------------------------------------------------------
#define TR 32

__device__ __forceinline__ void load_row6(const float* __restrict__ xp,
                                          int g, int col0,
                                          float& l, float4& v, float& r) {
    v = make_float4(0.f, 0.f, 0.f, 0.f);
    l = 0.f; r = 0.f;
    if ((unsigned)g < HH) {
        const float* rowp = xp + (size_t)g * WW;
        v = *reinterpret_cast<const float4*>(rowp + col0);
        if (col0 > 0)         l = __ldg(rowp + col0 - 1);
        if (col0 < WW - 4)    r = __ldg(rowp + col0 + 4);
    }
}

__global__ void __launch_bounds__(256) conv_kernel(
        const float* __restrict__ x,
        const float* __restrict__ fscale,
        const float* __restrict__ conv_bias,
        float* __restrict__ out) {
    const int bc   = blockIdx.y;          // 0..1023
    const int c    = bc & (CC - 1);
    const int row0 = blockIdx.x * TR;
    const int t    = threadIdx.x;         // 0..255
    const int cg   = t & 63;              // cols [4cg, 4cg+3]
    const int rs   = t >> 6;              // row slice 0..3 (8 rows each)
    const int g0   = row0 + rs * 8;
    const int col0 = cg * 4;

    const float* wp = g_wk + bc * KPOS;
    const float w0 = __ldg(wp + 0), w1v = __ldg(wp + 1), w2 = __ldg(wp + 2);
    const float w3 = __ldg(wp + 3), w4  = __ldg(wp + 4), w5 = __ldg(wp + 5);
    const float w6 = __ldg(wp + 6), w7  = __ldg(wp + 7), w8 = __ldg(wp + 8);
    const float cb = __ldg(conv_bias + c);
    const float fs = __ldg(fscale + c);

    const float* xp = x + (size_t)bc * HW;

    float  al, ar, bl, br;
    float4 av, bv;
    load_row6(xp, g0 - 1, col0, al, av, ar);
    load_row6(xp, g0,     col0, bl, bv, br);

    float* op = out + (size_t)bc * HW + (size_t)g0 * WW + col0;

    #pragma unroll
    for (int r = 0; r < 8; ++r) {
        float  cl, cr;
        float4 cv;
        load_row6(xp, g0 + r + 1, col0, cl, cv, cr);

        float4 o;
        {   // col0
            float y = cb + w0*al   + w1v*av.x + w2*av.y
                         + w3*bl   + w4 *bv.x + w5*bv.y
                         + w6*cl   + w7 *cv.x + w8*cv.y;
            const float xv = bv.x;
            o.x = (xv - y) * fs * xv + y;
        }
        {   // col0+1
            float y = cb + w0*av.x + w1v*av.y + w2*av.z
                         + w3*bv.x + w4 *bv.y + w5*bv.z
                         + w6*cv.x + w7 *cv.y + w8*cv.z;
            const float xv = bv.y;
            o.y = (xv - y) * fs * xv + y;
        }
        {   // col0+2
            float y = cb + w0*av.y + w1v*av.z + w2*av.w
                         + w3*bv.y + w4 *bv.z + w5*bv.w
                         + w6*cv.y + w7 *cv.z + w8*cv.w;
            const float xv = bv.z;
            o.z = (xv - y) * fs * xv + y;
        }
        {   // col0+3
            float y = cb + w0*av.z + w1v*av.w + w2*ar
                         + w3*bv.z + w4 *bv.w + w5*br
                         + w6*cv.z + w7 *cv.w + w8*cr;
            const float xv = bv.w;
            o.w = (xv - y) * fs * xv + y;
        }
        __stcs(reinterpret_cast<float4*>(op + (size_t)r * WW), o);

        al = bl; av = bv; ar = br;
        bl = cl; bv = cv; br = cr;
    }
}

// ---------------------------------------------------------------------------
// Launch: x, w1, b1, fscale, conv_bias (metadata order); out fp32.
// ---------------------------------------------------------------------------
extern "C" void kernel_launch(void* const* d_in, const int* in_sizes, int n_in,
                              void* d_out, int out_size) {
    const float* x         = (const float*)d_in[0];
    const float* w1        = (const float*)d_in[1];
    const float* b1        = (const float*)d_in[2];
    const float* fscale    = (const float*)d_in[3];
    const float* conv_bias = (const float*)d_in[4];
    float* out = (float*)d_out;

    avg_kernel<<<BB * CC, 256>>>(x);
    weight_kernel<<<BB, JDIM>>>(w1, b1);
    conv_kernel<<<dim3(HH / TR, BB * CC), 256>>>(x, fscale, conv_bias, out);
}

// round 8
// speedup vs baseline: 1.1964x; 1.0735x over previous
#include <cuda_runtime.h>

// Problem constants
#define BB 16
#define CC 64
#define HH 256
#define WW 256
#define HW (HH*WW)
#define KPOS 9          // 3x3
#define JDIM (CC*KPOS)  // 576

// Scratch (no allocation allowed in kernel_launch)
__device__ float g_avg[BB*CC];          // 1024 channel means

// ---------------------------------------------------------------------------
// Kernel 1: per-(b,c) spatial mean. At DRAM roofline (81% / 6.45 TB/s).
// ---------------------------------------------------------------------------
__global__ void avg_kernel(const float* __restrict__ x) {
    const int bc = blockIdx.x;
    const float4* p = reinterpret_cast<const float4*>(x + (size_t)bc * HW);
    const int t = threadIdx.x;     // 0..255
    float s = 0.f;
    #pragma unroll 8
    for (int i = 0; i < 64; ++i) {
        float4 v = p[i * 256 + t];
        s += (v.x + v.y) + (v.z + v.w);
    }
    __shared__ float red[256];
    red[t] = s;
    __syncthreads();
    #pragma unroll
    for (int off = 128; off > 0; off >>= 1) {
        if (t < off) red[t] += red[t + off];
        __syncthreads();
    }
    if (t == 0) g_avg[bc] = red[0] * (1.0f / (float)HW);
}

// ---------------------------------------------------------------------------
// Kernel 2: depthwise 3x3 conv + conv_bias, fused with (x-y)*fs*x + y.
// Each CTA computes its OWN 9 dynamic weights inline (9 lanes x 64-FMA dot
// + sigmoid, hidden behind the first row loads) — no separate weight kernel,
// no device-wide bubble.
// Conv body: PROVEN 79.8us @ 6084 GB/s (R6). 4 cols/thread, fully coalesced
// LDG.128/STG.128, no shuffles; halo = 2 scalar LDGs (L1 hits). Rolling
// 3-row x 6-col register window; streaming stores.
// ---------------------------------------------------------------------------
#define TR 32

__device__ __forceinline__ void load_row6(const float* __restrict__ xp,
                                          int g, int col0,
                                          float& l, float4& v, float& r) {
    v = make_float4(0.f, 0.f, 0.f, 0.f);
    l = 0.f; r = 0.f;
    if ((unsigned)g < HH) {
        const float* rowp = xp + (size_t)g * WW;
        v = *reinterpret_cast<const float4*>(rowp + col0);
        if (col0 > 0)         l = __ldg(rowp + col0 - 1);
        if (col0 < WW - 4)    r = __ldg(rowp + col0 + 4);
    }
}

__global__ void __launch_bounds__(256) conv_kernel(
        const float* __restrict__ x,
        const float* __restrict__ w1,
        const float* __restrict__ b1,
        const float* __restrict__ fscale,
        const float* __restrict__ conv_bias,
        float* __restrict__ out) {
    const int bc   = blockIdx.y;          // 0..1023
    const int b    = bc >> 6;
    const int c    = bc & (CC - 1);
    const int row0 = blockIdx.x * TR;
    const int t    = threadIdx.x;         // 0..255
    const int cg   = t & 63;              // cols [4cg, 4cg+3]
    const int rs   = t >> 6;              // row slice 0..3 (8 rows each)
    const int g0   = row0 + rs * 8;
    const int col0 = cg * 4;

    const float* xp = x + (size_t)bc * HW;

    // Issue the first two (long-latency) row loads before the weight dot,
    // so DRAM latency overlaps the 64-FMA weight computation.
    float  al, ar, bl, br;
    float4 av, bv;
    load_row6(xp, g0 - 1, col0, al, av, ar);
    load_row6(xp, g0,     col0, bl, bv, br);

    // Inline dynamic weights: lanes 0..8 of warp 0 each compute one of the
    // CTA's 9 weights: sigmoid(avg[b,:] . w1[c*9+k,:] + b1[c*9+k]).
    __shared__ float wsh[KPOS];
    if (t < KPOS) {
        const int j = c * KPOS + t;
        float acc = __ldg(b1 + j);
        const float* wr = w1 + (size_t)j * CC;
        const float* ap = g_avg + b * CC;
        #pragma unroll 16
        for (int k = 0; k < CC; ++k) acc += ap[k] * wr[k];
        wsh[t] = 1.0f / (1.0f + expf(-acc));
    }
    __syncthreads();

    const float w0 = wsh[0], w1v = wsh[1], w2 = wsh[2];
    const float w3 = wsh[3], w4  = wsh[4], w5 = wsh[5];
    const float w6 = wsh[6], w7  = wsh[7], w8 = wsh[8];
    const float cb = __ldg(conv_bias + c);
    const float fs = __ldg(fscale + c);

    float* op = out + (size_t)bc * HW + (size_t)g0 * WW + col0;

    #pragma unroll
    for (int r = 0; r < 8; ++r) {
        float  cl, cr;
        float4 cv;
        load_row6(xp, g0 + r + 1, col0, cl, cv, cr);

        float4 o;
        {   // col0
            float y = cb + w0*al   + w1v*av.x + w2*av.y
                         + w3*bl   + w4 *bv.x + w5*bv.y
                         + w6*cl   + w7 *cv.x + w8*cv.y;
            const float xv = bv.x;
            o.x = (xv - y) * fs * xv + y;
        }
        {   // col0+1
            float y = cb + w0*av.x + w1v*av.y + w2*av.z
                         + w3*bv.x + w4 *bv.y + w5*bv.z
                         + w6*cv.x + w7 *cv.y + w8*cv.z;
            const float xv = bv.y;
            o.y = (xv - y) * fs * xv + y;
        }
        {   // col0+2
            float y = cb + w0*av.y + w1v*av.z + w2*av.w
                         + w3*bv.y + w4 *bv.z + w5*bv.w
                         + w6*cv.y + w7 *cv.z + w8*cv.w;
            const float xv = bv.z;
            o.z = (xv - y) * fs * xv + y;
        }
        {   // col0+3
            float y = cb + w0*av.z + w1v*av.w + w2*ar
                         + w3*bv.z + w4 *bv.w + w5*br
                         + w6*cv.z + w7 *cv.w + w8*cr;
            const float xv = bv.w;
            o.w = (xv - y) * fs * xv + y;
        }
        __stcs(reinterpret_cast<float4*>(op + (size_t)r * WW), o);

        al = bl; av = bv; ar = br;
        bl = cl; bv = cv; br = cr;
    }
}

// ---------------------------------------------------------------------------
// Launch: x, w1, b1, fscale, conv_bias (metadata order); out fp32.
// ---------------------------------------------------------------------------
extern "C" void kernel_launch(void* const* d_in, const int* in_sizes, int n_in,
                              void* d_out, int out_size) {
    const float* x         = (const float*)d_in[0];
    const float* w1        = (const float*)d_in[1];
    const float* b1        = (const float*)d_in[2];
    const float* fscale    = (const float*)d_in[3];
    const float* conv_bias = (const float*)d_in[4];
    float* out = (float*)d_out;

    avg_kernel<<<BB * CC, 256>>>(x);
    conv_kernel<<<dim3(HH / TR, BB * CC), 256>>>(x, w1, b1, fscale, conv_bias, out);
}